// round 13
// baseline (speedup 1.0000x reference)
#include <cuda_runtime.h>
#include <cuda_bf16.h>
#include <math.h>
#include <stdint.h>

// ---------------- constants ----------------
#define SLOPE 0.1f
#define AZ 4000000          // per-s wavelet matrix elems (2000x2000)
#define CZ (1024 * 2048)    // per-s transposed feature matrix elems (padded K stride 2048)

// ---------------- scratch (device globals; no allocation) ----------------
__device__ float g_h1[16000 * 16 * 16];      // [b*N+n][t][16]
__device__ float g_o [16000 * 16 * 16];      // LN1 out, same layout
__device__ float g_enc[128 * 16000];         // [b*16+t][DM]
__device__ float g_qkv[128 * 96];            // [bt][96] (q|k|v)
__device__ float g_ctx[128 * 32];            // [bt][32]
__device__ float g_Xf [16000 * 128];         // [b*N+n][128]
__device__ float g_hyp[1024 * 2000];         // [c=(b*128+d)][n]  fp32, accumulated over s

// bf16 operands (all K-major; features [c][k] stride 2048)
__device__ __align__(16) __nv_bfloat16 g_wav16[4 * AZ], g_wi16[4 * AZ];
__device__ __align__(16) __nv_bfloat16 g_B1[CZ];
__device__ __align__(16) __nv_bfloat16 g_T1[4 * CZ];
__device__ __align__(16) __nv_bfloat16 g_F1[4 * CZ];
__device__ __align__(16) __nv_bfloat16 g_X2[4 * CZ];
__device__ __align__(16) __nv_bfloat16 g_T2[4 * CZ];

__device__ __forceinline__ float sigf(float x) { return 1.f / (1.f + expf(-x)); }

__device__ __forceinline__ uint32_t s2u(const void* p) {
    uint32_t a;
    asm("{ .reg .u64 t; cvta.to.shared.u64 t, %1; cvt.u32.u64 %0, t; }" : "=r"(a) : "l"(p));
    return a;
}
__device__ __forceinline__ void ldmat4(uint32_t* r, uint32_t addr) {
    asm volatile("ldmatrix.sync.aligned.m8n8.x4.shared.b16 {%0,%1,%2,%3}, [%4];"
                 : "=r"(r[0]), "=r"(r[1]), "=r"(r[2]), "=r"(r[3]) : "r"(addr));
}
__device__ __forceinline__ void mma16816(float* c, const uint32_t* a, const uint32_t* b) {
    asm volatile("mma.sync.aligned.m16n8k16.row.col.f32.bf16.bf16.f32 "
                 "{%0,%1,%2,%3}, {%4,%5,%6,%7}, {%8,%9}, {%0,%1,%2,%3};"
                 : "+f"(c[0]), "+f"(c[1]), "+f"(c[2]), "+f"(c[3])
                 : "r"(a[0]), "r"(a[1]), "r"(a[2]), "r"(a[3]), "r"(b[0]), "r"(b[1]));
}
__device__ __forceinline__ void cpasync16(uint32_t dst, const void* src, uint32_t bytes) {
    asm volatile("cp.async.cg.shared.global [%0], [%1], 16, %2;"
                 :: "r"(dst), "l"(src), "r"(bytes) : "memory");
}

// ---------------- K0: zero accumulators ----------------
__global__ void k_zero() {
    int i = blockIdx.x * blockDim.x + threadIdx.x;
    if (i < 512000) *(float4*)&g_hyp[i * 4] = make_float4(0.f, 0.f, 0.f, 0.f);
    if (i < 3072)   *(float4*)&g_qkv[i * 4] = make_float4(0.f, 0.f, 0.f, 0.f);
}

// ---------------- K-cvt: wavelets fp32 -> bf16 (vectorized) ----------------
__global__ void __launch_bounds__(256) k_cvt(const float* __restrict__ wav,
                                             const float* __restrict__ winv) {
    int stride = gridDim.x * 256 * 4;
    for (int i = (blockIdx.x * 256 + threadIdx.x) * 4; i < 16000000; i += stride) {
        float4 w = *(const float4*)&wav[i];
        float4 v = *(const float4*)&winv[i];
        __nv_bfloat162 w01 = __floats2bfloat162_rn(w.x, w.y);
        __nv_bfloat162 w23 = __floats2bfloat162_rn(w.z, w.w);
        __nv_bfloat162 v01 = __floats2bfloat162_rn(v.x, v.y);
        __nv_bfloat162 v23 = __floats2bfloat162_rn(v.z, v.w);
        *(__nv_bfloat162*)&g_wav16[i]     = w01;
        *(__nv_bfloat162*)&g_wav16[i + 2] = w23;
        *(__nv_bfloat162*)&g_wi16[i]      = v01;
        *(__nv_bfloat162*)&g_wi16[i + 2]  = v23;
    }
}

// ---------------- K1: embedding + LSTM1 (warp per (b,n) row) ----------------
__global__ void __launch_bounds__(128) k_lstm1(
                        const float* __restrict__ inp,
                        const float* __restrict__ embW, const float* __restrict__ embB,
                        const float* __restrict__ W1, const float* __restrict__ U1,
                        const float* __restrict__ b1) {
    __shared__ float sW[16 * 64], sU[16 * 64], sb[64], sEw[10 * 16], sEb[16];
    __shared__ float xs[4][16][16];
    __shared__ float zb[4][64], hs[4][16], cs[4][16];
    int tid = threadIdx.x;
    for (int i = tid; i < 1024; i += 128) { sW[i] = W1[i]; sU[i] = U1[i]; }
    for (int i = tid; i < 160; i += 128) sEw[i] = embW[i];
    if (tid < 64) sb[tid] = b1[tid];
    if (tid < 16) sEb[tid] = embB[tid];
    __syncthreads();
    int w = tid >> 5, lane = tid & 31;
    int gw = blockIdx.x * 4 + w;
    const float* irow = inp + (size_t)gw * 160;
    if (lane < 16) {
        for (int t = 0; t < 16; t++) {
            float acc = sEb[lane];
#pragma unroll
            for (int f = 0; f < 10; f++) acc += irow[t * 10 + f] * sEw[f * 16 + lane];
            xs[w][t][lane] = acc;
        }
        hs[w][lane] = 0.f; cs[w][lane] = 0.f;
    }
    __syncwarp();
    float* outr = g_h1 + (size_t)gw * 256;
    for (int t = 0; t < 16; t++) {
        int j1 = lane, j2 = lane + 32;
        float z1 = sb[j1], z2 = sb[j2];
#pragma unroll
        for (int e = 0; e < 16; e++) {
            float x = xs[w][t][e];
            z1 += x * sW[e * 64 + j1]; z2 += x * sW[e * 64 + j2];
        }
#pragma unroll
        for (int k = 0; k < 16; k++) {
            float hk = hs[w][k];
            z1 += hk * sU[k * 64 + j1]; z2 += hk * sU[k * 64 + j2];
        }
        zb[w][j1] = z1; zb[w][j2] = z2;
        __syncwarp();
        if (lane < 16) {
            float ig = zb[w][lane], fg = zb[w][16 + lane];
            float gg = zb[w][32 + lane], og = zb[w][48 + lane];
            float c = sigf(fg) * cs[w][lane] + sigf(ig) * tanhf(gg);
            float h = sigf(og) * tanhf(c);
            cs[w][lane] = c; hs[w][lane] = h;
            outr[t * 16 + lane] = h;
        }
        __syncwarp();
    }
}

// ---------------- K2: LayerNorm over N*H1=32000 per (b,t) ----------------
__global__ void __launch_bounds__(1024) k_ln1(const float* __restrict__ gg,
                                              const float* __restrict__ bb) {
    int bt = blockIdx.x; int b = bt >> 4, t = bt & 15;
    int tid = threadIdx.x;
    size_t base = (size_t)b * 512000 + t * 16;
    float s = 0.f, q = 0.f;
    for (int d = tid; d < 32000; d += 1024) {
        int n = d >> 4, j = d & 15;
        float v = g_h1[base + (size_t)n * 256 + j];
        s += v; q += v * v;
    }
    __shared__ float rs[1024], rq[1024];
    rs[tid] = s; rq[tid] = q; __syncthreads();
    for (int off = 512; off > 0; off >>= 1) {
        if (tid < off) { rs[tid] += rs[tid + off]; rq[tid] += rq[tid + off]; }
        __syncthreads();
    }
    float mu = rs[0] * (1.f / 32000.f);
    float var = rq[0] * (1.f / 32000.f) - mu * mu;
    float inv = rsqrtf(var + 1e-5f);
    for (int d = tid; d < 32000; d += 1024) {
        int n = d >> 4, j = d & 15;
        size_t a = base + (size_t)n * 256 + j;
        g_o[a] = (g_h1[a] - mu) * inv * gg[d] + bb[d];
    }
}

// ---------------- K3: LSTM2 (warp per row) ----------------
__global__ void __launch_bounds__(128) k_lstm2(
                        const float* __restrict__ W2, const float* __restrict__ U2,
                        const float* __restrict__ b2) {
    __shared__ float sW[16 * 32], sU[8 * 32], sb[32];
    __shared__ float xs[4][16][16];
    __shared__ float zb[4][32], hs[4][8], cs[4][8];
    int tid = threadIdx.x;
    for (int i = tid; i < 512; i += 128) sW[i] = W2[i];
    for (int i = tid; i < 256; i += 128) sU[i] = U2[i];
    if (tid < 32) sb[tid] = b2[tid];
    __syncthreads();
    int w = tid >> 5, lane = tid & 31;
    int gw = blockIdx.x * 4 + w;
    for (int idx = lane; idx < 256; idx += 32)
        xs[w][idx >> 4][idx & 15] = g_o[(size_t)gw * 256 + idx];
    if (lane < 8) { hs[w][lane] = 0.f; cs[w][lane] = 0.f; }
    __syncwarp();
    int b = gw / 2000, n = gw - b * 2000;
    for (int t = 0; t < 16; t++) {
        float z = sb[lane];
#pragma unroll
        for (int e = 0; e < 16; e++) z += xs[w][t][e] * sW[e * 32 + lane];
#pragma unroll
        for (int k = 0; k < 8; k++) z += hs[w][k] * sU[k * 32 + lane];
        zb[w][lane] = z;
        __syncwarp();
        if (lane < 8) {
            float ig = zb[w][lane], fg = zb[w][8 + lane];
            float gg = zb[w][16 + lane], og = zb[w][24 + lane];
            float c = sigf(fg) * cs[w][lane] + sigf(ig) * tanhf(gg);
            float h = sigf(og) * tanhf(c);
            cs[w][lane] = c; hs[w][lane] = h;
            g_enc[((size_t)b * 16 + t) * 16000 + n * 8 + lane] = h;
        }
        __syncwarp();
    }
}

// ---------------- K4: QKV projection ----------------
__global__ void __launch_bounds__(256) k_qkv(const float* __restrict__ Wq,
                                             const float* __restrict__ Wk,
                                             const float* __restrict__ Wv) {
    __shared__ float As[10][128];
    __shared__ float Bs[10][96];
    int tid = threadIdx.x; int tx = tid & 15, ty = tid >> 4;
    int k0 = blockIdx.x * 250;
    float acc[8][6];
#pragma unroll
    for (int i = 0; i < 8; i++)
#pragma unroll
        for (int j = 0; j < 6; j++) acc[i][j] = 0.f;
    for (int kk0 = 0; kk0 < 250; kk0 += 10) {
        for (int idx = tid; idx < 1280; idx += 256) {
            int r = idx / 10, k = idx % 10;
            As[k][r] = g_enc[(size_t)r * 16000 + k0 + kk0 + k];
        }
        for (int idx = tid; idx < 960; idx += 256) {
            int k = idx / 96, c = idx % 96;
            int wcol = c & 31; int sel = c >> 5;
            const float* W = (sel == 0) ? Wq : ((sel == 1) ? Wk : Wv);
            Bs[k][c] = W[(size_t)(k0 + kk0 + k) * 32 + wcol];
        }
        __syncthreads();
#pragma unroll
        for (int k = 0; k < 10; k++) {
            float a[8], bv[6];
#pragma unroll
            for (int i = 0; i < 8; i++) a[i] = As[k][ty * 8 + i];
#pragma unroll
            for (int j = 0; j < 6; j++) bv[j] = Bs[k][tx * 6 + j];
#pragma unroll
            for (int i = 0; i < 8; i++)
#pragma unroll
                for (int j = 0; j < 6; j++) acc[i][j] += a[i] * bv[j];
        }
        __syncthreads();
    }
#pragma unroll
    for (int i = 0; i < 8; i++)
#pragma unroll
        for (int j = 0; j < 6; j++)
            atomicAdd(&g_qkv[(ty * 8 + i) * 96 + tx * 6 + j], acc[i][j]);
}

// ---------------- K5: causal attention ----------------
__global__ void k_attn() {
    int bh = blockIdx.x; int b = bh >> 2, h = bh & 3;
    __shared__ float kk[16][8], vv[16][8];
    int lane = threadIdx.x;
    for (int idx = lane; idx < 128; idx += 32) {
        int t = idx >> 3, d = idx & 7;
        kk[t][d] = g_qkv[(b * 16 + t) * 96 + 32 + h * 8 + d];
        vv[t][d] = g_qkv[(b * 16 + t) * 96 + 64 + h * 8 + d];
    }
    __syncwarp();
    if (lane < 16) {
        int i = lane;
        float qv[8];
#pragma unroll
        for (int d = 0; d < 8; d++) qv[d] = g_qkv[(b * 16 + i) * 96 + h * 8 + d];
        float sc[16]; float mx = -1e30f;
#pragma unroll
        for (int j = 0; j < 16; j++) {
            if (j <= i) {
                float s = 0.f;
#pragma unroll
                for (int d = 0; d < 8; d++) s += qv[d] * kk[j][d];
                s *= 0.35355339059327373f;
                sc[j] = s; mx = fmaxf(mx, s);
            } else sc[j] = -1e30f;
        }
        float den = 0.f, p[16];
#pragma unroll
        for (int j = 0; j < 16; j++) {
            p[j] = (j <= i) ? expf(sc[j] - mx) : 0.f;
            den += p[j];
        }
        float rden = 1.f / den;
#pragma unroll
        for (int d = 0; d < 8; d++) {
            float c = 0.f;
#pragma unroll
            for (int j = 0; j < 16; j++) c += p[j] * vv[j][d];
            g_ctx[(b * 16 + i) * 32 + h * 8 + d] = c * rden;
        }
    }
}

// ---------------- K6: O-proj + residual + LN2, scatter to Xf ----------------
__global__ void __launch_bounds__(256) k_oproj(const float* __restrict__ Wo,
                                               const float* __restrict__ gg,
                                               const float* __restrict__ bb) {
    int bt = blockIdx.x; int b = bt >> 4, t = bt & 15;
    int tid = threadIdx.x;
    __shared__ float cs2[32];
    if (tid < 32) cs2[tid] = g_ctx[bt * 32 + tid];
    __syncthreads();
    float* er = g_enc + (size_t)bt * 16000;
    float s = 0.f, q = 0.f;
    for (int d = tid; d < 16000; d += 256) {
        float y = er[d];
#pragma unroll
        for (int j = 0; j < 32; j++) y += cs2[j] * Wo[(size_t)j * 16000 + d];
        er[d] = y; s += y; q += y * y;
    }
    __shared__ float rs[256], rq[256];
    rs[tid] = s; rq[tid] = q; __syncthreads();
    for (int off = 128; off > 0; off >>= 1) {
        if (tid < off) { rs[tid] += rs[tid + off]; rq[tid] += rq[tid + off]; }
        __syncthreads();
    }
    float mu = rs[0] * (1.f / 16000.f);
    float var = rq[0] * (1.f / 16000.f) - mu * mu;
    float inv = rsqrtf(var + 1e-5f);
    for (int d = tid; d < 16000; d += 256) {
        float y = er[d];
        float v = (y - mu) * inv * gg[d] + bb[d];
        int n = d >> 3, j = d & 7;
        g_Xf[((size_t)b * 2000 + n) * 128 + t * 8 + j] = v;
    }
}

// ---------------- K7a: theta1: X1^T[c=(b,d)][m] = sum_e Xf[b,m,e] th1[e,d] ----------------
__global__ void __launch_bounds__(128) k_theta1(const float* __restrict__ th) {
    int m0 = blockIdx.x * 16; int b = blockIdx.y;
    __shared__ float As[16][128];
    int tid = threadIdx.x;
    for (int idx = tid; idx < 2048; idx += 128) {
        int mm = idx >> 7, e = idx & 127;
        As[mm][e] = g_Xf[((size_t)b * 2000 + m0 + mm) * 128 + e];
    }
    __syncthreads();
    float acc[16];
#pragma unroll
    for (int mm = 0; mm < 16; mm++) acc[mm] = 0.f;
    int d = tid;
    for (int e = 0; e < 128; e++) {
        float tv = th[e * 128 + d];
#pragma unroll
        for (int mm = 0; mm < 16; mm++) acc[mm] += As[mm][e] * tv;
    }
#pragma unroll
    for (int mm = 0; mm < 16; mm++)
        g_B1[((size_t)(b * 128 + d)) * 2048 + m0 + mm] = __float2bfloat16(acc[mm]);
}

// ---------------- K7b: theta2: X2^T[s][(b,e)][n] = sum_d F1^T[s][(b,d)][n] th2[d,e] ----------------
__global__ void __launch_bounds__(128) k_theta2(const float* __restrict__ th) {
    int n0 = blockIdx.x * 16; int b = blockIdx.y; int z = blockIdx.z;
    const __nv_bfloat16* F = g_F1 + (size_t)z * CZ;
    __nv_bfloat16* X = g_X2 + (size_t)z * CZ;
    __shared__ float As[16][128];     // As[nn][d]
    int tid = threadIdx.x;
    for (int idx = tid; idx < 2048; idx += 128) {
        int d = idx >> 4, nn = idx & 15;
        As[nn][d] = __bfloat162float(F[((size_t)(b * 128 + d)) * 2048 + n0 + nn]);
    }
    __syncthreads();
    float acc[16];
#pragma unroll
    for (int nn = 0; nn < 16; nn++) acc[nn] = 0.f;
    int e = tid;
    for (int d = 0; d < 128; d++) {
        float tv = th[d * 128 + e];
#pragma unroll
        for (int nn = 0; nn < 16; nn++) acc[nn] += As[nn][d] * tv;
    }
#pragma unroll
    for (int nn = 0; nn < 16; nn++)
        X[((size_t)(b * 128 + e)) * 2048 + n0 + nn] = __float2bfloat16(acc[nn]);
}

// ---------------- K8: bf16 HMMA GEMM  C[2000,1024] = op(A[2000,2000] @ B^T) ----------------
// A bf16 [m][k] k-contig; B bf16 [c][k] k-contig stride 2048; C stored [c][m].
// bSel: 0=B1(shared) 1=T1 2=X2 3=T2 ; oSel: 0=hyp(atomic) 1=T1 2=F1 3=T2
// 3-stage cp.async pipeline, prefetch distance 2, one __syncthreads per chunk.
#define ROWB 80
#define MATB (128 * ROWB)       // 10240
#define STGB (2 * MATB)         // 20480 per stage (A + B)
#define NSTG 3
#define KCH 63                  // ceil(2000/32)
__global__ void __launch_bounds__(256) k_mmagemm(
        const __nv_bfloat16* __restrict__ Abase, int bSel, int oSel,
        const float* __restrict__ rowscale, const float* __restrict__ parv, int leaky) {
    extern __shared__ char sm[];
    uint32_t sb = s2u(sm);
    int tid = threadIdx.x, wid = tid >> 5, lane = tid & 31;
    int z = blockIdx.z;
    int m0 = blockIdx.y * 128, n0 = blockIdx.x * 128;

    const __nv_bfloat16* Ap = Abase + (size_t)z * AZ;
    size_t bz = (size_t)z * CZ;
    const __nv_bfloat16* Bp;
    if (bSel == 0)      Bp = g_B1;
    else if (bSel == 1) Bp = g_T1 + bz;
    else if (bSel == 2) Bp = g_X2 + bz;
    else                Bp = g_T2 + bz;

    float acc[4][4][4];
#pragma unroll
    for (int i = 0; i < 4; i++)
#pragma unroll
        for (int j = 0; j < 4; j++)
#pragma unroll
            for (int r = 0; r < 4; r++) acc[i][j][r] = 0.f;

    // ---- async load of one 32-K chunk (A + B, 1024 x 16B) ----
    auto load_chunk = [&](int ck, int buf) {
        int k0 = ck * 32;
#pragma unroll
        for (int i = 0; i < 4; i++) {
            int q = i * 256 + tid;                  // 1024 16B-chunks
            int g = q & 3, r = (q >> 2) & 127, mat = q >> 9;
            uint32_t dst = sb + buf * STGB + mat * MATB + r * ROWB + g * 16;
            int k = k0 + g * 8;
            const __nv_bfloat16* src;
            bool v;
            if (mat == 0) {
                int m = m0 + r;
                v = (m < 2000) && (k < 2000);
                src = Ap + (v ? ((size_t)m * 2000 + k) : 0);
            } else {
                v = (k < 2000);
                src = Bp + (size_t)(n0 + r) * 2048 + k;
            }
            cpasync16(dst, src, v ? 16u : 0u);
        }
    };

    load_chunk(0, 0);
    asm volatile("cp.async.commit_group;" ::: "memory");
    load_chunk(1, 1);
    asm volatile("cp.async.commit_group;" ::: "memory");

    int wm = (wid & 1) * 64;        // warp m offset (2 x 64)
    int wn = (wid >> 1) * 32;       // warp n offset (4 x 32)
    uint32_t rsel = (lane & 15);    // ldmatrix row-within-16
    uint32_t csel = ((lane >> 4) & 1) * 16;  // 8-bf16 col group (bytes)

    int buf = 0, nbuf = 2;
    for (int ck = 0; ck < KCH; ck++) {
        asm volatile("cp.async.wait_group 1;" ::: "memory");
        __syncthreads();
        if (ck + 2 < KCH) load_chunk(ck + 2, nbuf);
        asm volatile("cp.async.commit_group;" ::: "memory");
        uint32_t base = sb + buf * STGB;
#pragma unroll
        for (int sub = 0; sub < 2; sub++) {
            uint32_t cb = csel + sub * 32;
            uint32_t ah[4][4], bh[4][2];
#pragma unroll
            for (int mi = 0; mi < 4; mi++) {
                uint32_t ad = base + (wm + mi * 16 + rsel) * ROWB + cb;
                ldmat4(ah[mi], ad);
            }
#pragma unroll
            for (int nj = 0; nj < 2; nj++) {
                uint32_t r4[4];
                uint32_t bd = base + MATB + (wn + nj * 16 + rsel) * ROWB + cb;
                ldmat4(r4, bd);
                bh[nj * 2][0] = r4[0]; bh[nj * 2][1] = r4[2];
                bh[nj * 2 + 1][0] = r4[1]; bh[nj * 2 + 1][1] = r4[3];
            }
#pragma unroll
            for (int mi = 0; mi < 4; mi++)
#pragma unroll
                for (int ni = 0; ni < 4; ni++)
                    mma16816(acc[mi][ni], ah[mi], bh[ni]);
        }
        buf = (buf + 1 == NSTG) ? 0 : buf + 1;
        nbuf = (nbuf + 1 == NSTG) ? 0 : nbuf + 1;
    }
    __syncthreads();

    // ---- epilogue: scale / leaky / alpha, two 64-n passes through 32KB SMEM stage ----
    float alpha = parv ? parv[z] : 1.f;
    float* st = (float*)sm;                 // 64*128 fp32 = 32 KB per pass
    int mlo0 = wm + (lane >> 2);
    float rsv[8];
#pragma unroll
    for (int mi = 0; mi < 4; mi++) {
        int mlo = mlo0 + mi * 16;
        rsv[mi * 2]     = rowscale ? ((m0 + mlo < 2000) ? rowscale[m0 + mlo] : 0.f) : 1.f;
        rsv[mi * 2 + 1] = rowscale ? ((m0 + mlo + 8 < 2000) ? rowscale[m0 + mlo + 8] : 0.f) : 1.f;
    }
    __nv_bfloat16* C = nullptr;
    if (oSel == 1)      C = g_T1 + bz;
    else if (oSel == 2) C = g_F1 + bz;
    else if (oSel == 3) C = g_T2 + bz;

    for (int p = 0; p < 2; p++) {
        if ((wn >> 6) == p) {
            int wnl = wn - p * 64;
#pragma unroll
            for (int mi = 0; mi < 4; mi++) {
                int mlo = mlo0 + mi * 16;
#pragma unroll
                for (int ni = 0; ni < 4; ni++) {
                    int nl = wnl + ni * 8 + (lane & 3) * 2;
#pragma unroll
                    for (int r = 0; r < 4; r++) {
                        float v = acc[mi][ni][r];
                        int ml = (r < 2) ? mlo : (mlo + 8);
                        v *= rsv[mi * 2 + (r < 2 ? 0 : 1)];
                        if (leaky) v = (v > 0.f) ? v : SLOPE * v;
                        v *= alpha;
                        st[(nl + (r & 1)) * 128 + ml] = v;
                    }
                }
            }
        }
        __syncthreads();
        if (oSel == 0) {
            for (int idx = tid; idx < 8192; idx += 256) {
                int nl = idx >> 7, ml = idx & 127;
                if (m0 + ml < 2000)
                    atomicAdd(&g_hyp[(size_t)(n0 + p * 64 + nl) * 2000 + m0 + ml], st[idx]);
            }
        } else {
            for (int idx = tid; idx < 8192; idx += 256) {
                int nl = idx >> 7, ml = idx & 127;
                C[(size_t)(n0 + p * 64 + nl) * 2048 + m0 + ml] = __float2bfloat16(st[idx]);
            }
        }
        __syncthreads();
    }
}

// ---------------- K9: final MLP ----------------
__global__ void __launch_bounds__(256) k_mlp(
                      const float* __restrict__ w1, const float* __restrict__ b1m,
                      const float* __restrict__ w2, const float* __restrict__ b2m,
                      float* __restrict__ out) {
    __shared__ float sw1[256], sb1[16], sw2[16], sb2;
    int tid = threadIdx.x;
    sw1[tid] = w1[tid];
    if (tid < 16) { sb1[tid] = b1m[tid]; sw2[tid] = w2[tid]; }
    if (tid == 0) sb2 = b2m[0];
    __syncthreads();
    int idx = blockIdx.x * 256 + tid;
    int b = idx / 32000; int rem = idx - b * 32000;
    int n = rem >> 4; int t = rem & 15;
    float cat[16];
    const float* xf = g_Xf + ((size_t)b * 2000 + n) * 128 + t * 8;
#pragma unroll
    for (int j = 0; j < 8; j++) {
        cat[j] = xf[j];
        cat[8 + j] = g_hyp[(size_t)(b * 128 + t * 8 + j) * 2000 + n];
    }
    float acc = sb2;
#pragma unroll
    for (int i = 0; i < 16; i++) {
        float mi = sb1[i];
#pragma unroll
        for (int j = 0; j < 16; j++) mi += cat[j] * sw1[j * 16 + i];
        mi = fmaxf(mi, 0.f);
        acc += mi * sw2[i];
    }
    out[idx] = acc;
}

// ---------------- launch ----------------
#define GSMEM (NSTG * STGB)   // 61440

extern "C" void kernel_launch(void* const* d_in, const int* in_sizes, int n_in,
                              void* d_out, int out_size) {
    const float* inp  = (const float*)d_in[0];
    const float* embW = (const float*)d_in[1];
    const float* embB = (const float*)d_in[2];
    const float* W1   = (const float*)d_in[3];
    const float* U1   = (const float*)d_in[4];
    const float* b1   = (const float*)d_in[5];
    const float* ln1g = (const float*)d_in[6];
    const float* ln1b = (const float*)d_in[7];
    const float* W2   = (const float*)d_in[8];
    const float* U2   = (const float*)d_in[9];
    const float* b2   = (const float*)d_in[10];
    const float* Wq   = (const float*)d_in[11];
    const float* Wk   = (const float*)d_in[12];
    const float* Wv   = (const float*)d_in[13];
    const float* Wo   = (const float*)d_in[14];
    const float* ln2g = (const float*)d_in[15];
    const float* ln2b = (const float*)d_in[16];
    const float* par  = (const float*)d_in[17];
    const float* th1  = (const float*)d_in[18];
    const float* dg1  = (const float*)d_in[19];
    const float* th2  = (const float*)d_in[20];
    const float* dg2  = (const float*)d_in[21];
    const float* m1W  = (const float*)d_in[22];
    const float* m1b  = (const float*)d_in[23];
    const float* m2W  = (const float*)d_in[24];
    const float* m2b  = (const float*)d_in[25];
    const float* wav  = (const float*)d_in[26];
    const float* winv = (const float*)d_in[27];
    float* out = (float*)d_out;

    cudaFuncSetAttribute(k_mmagemm, cudaFuncAttributeMaxDynamicSharedMemorySize, GSMEM);

    __nv_bfloat16* wi16;  cudaGetSymbolAddress((void**)&wi16,  g_wi16);
    __nv_bfloat16* wav16; cudaGetSymbolAddress((void**)&wav16, g_wav16);

    k_zero<<<2000, 256>>>();
    k_cvt<<<4096, 256>>>(wav, winv);
    k_lstm1<<<4000, 128>>>(inp, embW, embB, W1, U1, b1);
    k_ln1<<<128, 1024>>>(ln1g, ln1b);
    k_lstm2<<<4000, 128>>>(W2, U2, b2);
    k_qkv<<<64, 256>>>(Wq, Wk, Wv);
    k_attn<<<32, 32>>>();
    k_oproj<<<128, 256>>>(Wo, ln2g, ln2b);

    // hypergraph, layer 1
    k_theta1<<<dim3(125, 8), 128>>>(th1);                                          // B1 = (Xf@th1)^T
    k_mmagemm<<<dim3(8, 16, 4), 256, GSMEM>>>(wi16,  0, 1, dg1, nullptr, 0);       // T1 = diag1*(Winv@X1)
    k_mmagemm<<<dim3(8, 16, 4), 256, GSMEM>>>(wav16, 1, 2, nullptr, nullptr, 1);   // F1 = leaky(W@T1)
    // layer 2
    k_theta2<<<dim3(125, 8, 4), 128>>>(th2);                                       // X2 = F1@th2
    k_mmagemm<<<dim3(8, 16, 4), 256, GSMEM>>>(wi16,  2, 3, dg2, nullptr, 0);       // T2 = diag2*(Winv@X2)
    k_mmagemm<<<dim3(8, 16, 4), 256, GSMEM>>>(wav16, 3, 0, nullptr, par, 1);       // hyp += par*leaky(W@T2)

    k_mlp<<<1000, 256>>>(m1W, m1b, m2W, m2b, out);
}

// round 14
// speedup vs baseline: 1.1305x; 1.1305x over previous
#include <cuda_runtime.h>
#include <cuda_bf16.h>
#include <math.h>
#include <stdint.h>

// ---------------- constants ----------------
#define SLOPE 0.1f
#define KC 32                       // 64-wide K chunks (2048 padded K)
#define WZ (KC * 2048 * 64)         // wavelet blocked elems per z  (4,194,304)
#define FZ (KC * 1024 * 64)         // feature blocked elems per z  (2,097,152)

// ---------------- scratch (device globals; no allocation) ----------------
__device__ float g_h1[16000 * 16 * 16];      // [b*N+n][t][16]
__device__ float g_o [16000 * 16 * 16];      // LN1 out, same layout
__device__ float g_enc[128 * 16000];         // [b*16+t][DM]
__device__ float g_qkv[128 * 96];            // [bt][96] (q|k|v)
__device__ float g_ctx[128 * 32];            // [bt][32]
__device__ float g_Xf [16000 * 128];         // [b*N+n][128]
__device__ float g_hyp[1024 * 2000];         // [c=(b*128+d)][n]  fp32, accumulated over s

// blocked + SW128-swizzled bf16 operands: [kc][row][64 k], 16KB-contiguous chunks
__device__ __align__(16) __nv_bfloat16 g_wavB[4 * WZ], g_wiB[4 * WZ];
__device__ __align__(16) __nv_bfloat16 g_B1b[FZ];
__device__ __align__(16) __nv_bfloat16 g_T1b[4 * FZ];
__device__ __align__(16) __nv_bfloat16 g_F1b[4 * FZ];
__device__ __align__(16) __nv_bfloat16 g_X2b[4 * FZ];
__device__ __align__(16) __nv_bfloat16 g_T2b[4 * FZ];

__device__ __forceinline__ float sigf(float x) { return 1.f / (1.f + expf(-x)); }

__device__ __forceinline__ uint32_t s2u(const void* p) {
    uint32_t a;
    asm("{ .reg .u64 t; cvta.to.shared.u64 t, %1; cvt.u32.u64 %0, t; }" : "=r"(a) : "l"(p));
    return a;
}
// blocked elem index: wavelet matrices (2048 rows per kc)
__device__ __forceinline__ size_t wblk(int n, int k) {
    int kc = k >> 6;
    int kb = ((k & 63) * 2) ^ ((n & 7) << 4);     // swizzled byte-in-row
    return (((size_t)(kc * 2048 + n)) << 6) + (kb >> 1);
}
// blocked elem index: feature matrices (1024 rows per kc)
__device__ __forceinline__ size_t fblk(int c, int k) {
    int kc = k >> 6;
    int kb = ((k & 63) * 2) ^ ((c & 7) << 4);
    return (((size_t)(kc * 1024 + c)) << 6) + (kb >> 1);
}
__device__ __forceinline__ void ldmat4(uint32_t* r, uint32_t addr) {
    asm volatile("ldmatrix.sync.aligned.m8n8.x4.shared.b16 {%0,%1,%2,%3}, [%4];"
                 : "=r"(r[0]), "=r"(r[1]), "=r"(r[2]), "=r"(r[3]) : "r"(addr));
}
__device__ __forceinline__ void mma16816(float* c, const uint32_t* a, const uint32_t* b) {
    asm volatile("mma.sync.aligned.m16n8k16.row.col.f32.bf16.bf16.f32 "
                 "{%0,%1,%2,%3}, {%4,%5,%6,%7}, {%8,%9}, {%0,%1,%2,%3};"
                 : "+f"(c[0]), "+f"(c[1]), "+f"(c[2]), "+f"(c[3])
                 : "r"(a[0]), "r"(a[1]), "r"(a[2]), "r"(a[3]), "r"(b[0]), "r"(b[1]));
}
#define MBAR_INIT(addr, cnt) \
    asm volatile("mbarrier.init.shared.b64 [%0], %1;" :: "r"(addr), "r"(cnt) : "memory")
#define MBAR_EXPECT(addr, tx) \
    asm volatile("mbarrier.arrive.expect_tx.shared.b64 _, [%0], %1;" :: "r"(addr), "r"(tx) : "memory")
#define MBAR_WAIT(addr, parity) do { \
    uint32_t _m = (addr), _p = (parity), _d; \
    asm volatile("{\n\t.reg .pred p;\n\t" \
        "mbarrier.try_wait.parity.acquire.cta.shared::cta.b64 p, [%1], %2;\n\t" \
        "selp.b32 %0, 1, 0, p;\n\t}" : "=r"(_d) : "r"(_m), "r"(_p) : "memory"); \
    if (!_d) { \
        asm volatile("{\n\t.reg .pred P1;\n\t" \
            "WL%=:\n\t" \
            "mbarrier.try_wait.parity.acquire.cta.shared::cta.b64 P1, [%0], %1, 0x989680;\n\t" \
            "@P1 bra.uni WD%=;\n\t" \
            "bra.uni WL%=;\n\t" \
            "WD%=:\n\t}" :: "r"(_m), "r"(_p) : "memory"); \
    } \
} while (0)
__device__ __forceinline__ void bulk_g2s(uint32_t dst, const void* src, uint32_t bytes,
                                         uint32_t mbar) {
    asm volatile("cp.async.bulk.shared::cta.global.mbarrier::complete_tx::bytes "
                 "[%0], [%1], %2, [%3];"
                 :: "r"(dst), "l"(src), "r"(bytes), "r"(mbar) : "memory");
}

// ---------------- K0: zero accumulators ----------------
__global__ void k_zero() {
    int i = blockIdx.x * blockDim.x + threadIdx.x;
    if (i < 512000) *(float4*)&g_hyp[i * 4] = make_float4(0.f, 0.f, 0.f, 0.f);
    if (i < 3072)   *(float4*)&g_qkv[i * 4] = make_float4(0.f, 0.f, 0.f, 0.f);
}

// ---------------- K-cvtB: wavelets fp32 -> blocked swizzled bf16 ----------------
__global__ void __launch_bounds__(256) k_cvtB(const float* __restrict__ wav,
                                              const float* __restrict__ winv) {
    long long idx = (long long)blockIdx.x * 256 + threadIdx.x;   // (z, n, kpair)
    if (idx >= 8000000LL) return;
    int kp = (int)(idx % 1000);
    int rest = (int)(idx / 1000);
    int n = rest % 2000;
    int z = rest / 2000;
    int k = kp * 2;
    size_t src = (size_t)z * 4000000 + (size_t)n * 2000 + k;
    float2 w = *(const float2*)&wav[src];
    float2 v = *(const float2*)&winv[src];
    size_t dst = (size_t)z * WZ + wblk(n, k);
    *(__nv_bfloat162*)&g_wavB[dst] = __floats2bfloat162_rn(w.x, w.y);
    *(__nv_bfloat162*)&g_wiB[dst]  = __floats2bfloat162_rn(v.x, v.y);
}

// ---------------- K1: embedding + LSTM1 (warp per (b,n) row) ----------------
__global__ void __launch_bounds__(128) k_lstm1(
                        const float* __restrict__ inp,
                        const float* __restrict__ embW, const float* __restrict__ embB,
                        const float* __restrict__ W1, const float* __restrict__ U1,
                        const float* __restrict__ b1) {
    __shared__ float sW[16 * 64], sU[16 * 64], sb[64], sEw[10 * 16], sEb[16];
    __shared__ float xs[4][16][16];
    __shared__ float zb[4][64], hs[4][16], cs[4][16];
    int tid = threadIdx.x;
    for (int i = tid; i < 1024; i += 128) { sW[i] = W1[i]; sU[i] = U1[i]; }
    for (int i = tid; i < 160; i += 128) sEw[i] = embW[i];
    if (tid < 64) sb[tid] = b1[tid];
    if (tid < 16) sEb[tid] = embB[tid];
    __syncthreads();
    int w = tid >> 5, lane = tid & 31;
    int gw = blockIdx.x * 4 + w;
    const float* irow = inp + (size_t)gw * 160;
    if (lane < 16) {
        for (int t = 0; t < 16; t++) {
            float acc = sEb[lane];
#pragma unroll
            for (int f = 0; f < 10; f++) acc += irow[t * 10 + f] * sEw[f * 16 + lane];
            xs[w][t][lane] = acc;
        }
        hs[w][lane] = 0.f; cs[w][lane] = 0.f;
    }
    __syncwarp();
    float* outr = g_h1 + (size_t)gw * 256;
    for (int t = 0; t < 16; t++) {
        int j1 = lane, j2 = lane + 32;
        float z1 = sb[j1], z2 = sb[j2];
#pragma unroll
        for (int e = 0; e < 16; e++) {
            float x = xs[w][t][e];
            z1 += x * sW[e * 64 + j1]; z2 += x * sW[e * 64 + j2];
        }
#pragma unroll
        for (int k = 0; k < 16; k++) {
            float hk = hs[w][k];
            z1 += hk * sU[k * 64 + j1]; z2 += hk * sU[k * 64 + j2];
        }
        zb[w][j1] = z1; zb[w][j2] = z2;
        __syncwarp();
        if (lane < 16) {
            float ig = zb[w][lane], fg = zb[w][16 + lane];
            float gg = zb[w][32 + lane], og = zb[w][48 + lane];
            float c = sigf(fg) * cs[w][lane] + sigf(ig) * tanhf(gg);
            float h = sigf(og) * tanhf(c);
            cs[w][lane] = c; hs[w][lane] = h;
            outr[t * 16 + lane] = h;
        }
        __syncwarp();
    }
}

// ---------------- K2: LayerNorm over N*H1=32000 per (b,t) ----------------
__global__ void __launch_bounds__(1024) k_ln1(const float* __restrict__ gg,
                                              const float* __restrict__ bb) {
    int bt = blockIdx.x; int b = bt >> 4, t = bt & 15;
    int tid = threadIdx.x;
    size_t base = (size_t)b * 512000 + t * 16;
    float s = 0.f, q = 0.f;
    for (int d = tid; d < 32000; d += 1024) {
        int n = d >> 4, j = d & 15;
        float v = g_h1[base + (size_t)n * 256 + j];
        s += v; q += v * v;
    }
    __shared__ float rs[1024], rq[1024];
    rs[tid] = s; rq[tid] = q; __syncthreads();
    for (int off = 512; off > 0; off >>= 1) {
        if (tid < off) { rs[tid] += rs[tid + off]; rq[tid] += rq[tid + off]; }
        __syncthreads();
    }
    float mu = rs[0] * (1.f / 32000.f);
    float var = rq[0] * (1.f / 32000.f) - mu * mu;
    float inv = rsqrtf(var + 1e-5f);
    for (int d = tid; d < 32000; d += 1024) {
        int n = d >> 4, j = d & 15;
        size_t a = base + (size_t)n * 256 + j;
        g_o[a] = (g_h1[a] - mu) * inv * gg[d] + bb[d];
    }
}

// ---------------- K3: LSTM2 (warp per row) ----------------
__global__ void __launch_bounds__(128) k_lstm2(
                        const float* __restrict__ W2, const float* __restrict__ U2,
                        const float* __restrict__ b2) {
    __shared__ float sW[16 * 32], sU[8 * 32], sb[32];
    __shared__ float xs[4][16][16];
    __shared__ float zb[4][32], hs[4][8], cs[4][8];
    int tid = threadIdx.x;
    for (int i = tid; i < 512; i += 128) sW[i] = W2[i];
    for (int i = tid; i < 256; i += 128) sU[i] = U2[i];
    if (tid < 32) sb[tid] = b2[tid];
    __syncthreads();
    int w = tid >> 5, lane = tid & 31;
    int gw = blockIdx.x * 4 + w;
    for (int idx = lane; idx < 256; idx += 32)
        xs[w][idx >> 4][idx & 15] = g_o[(size_t)gw * 256 + idx];
    if (lane < 8) { hs[w][lane] = 0.f; cs[w][lane] = 0.f; }
    __syncwarp();
    int b = gw / 2000, n = gw - b * 2000;
    for (int t = 0; t < 16; t++) {
        float z = sb[lane];
#pragma unroll
        for (int e = 0; e < 16; e++) z += xs[w][t][e] * sW[e * 32 + lane];
#pragma unroll
        for (int k = 0; k < 8; k++) z += hs[w][k] * sU[k * 32 + lane];
        zb[w][lane] = z;
        __syncwarp();
        if (lane < 8) {
            float ig = zb[w][lane], fg = zb[w][8 + lane];
            float gg = zb[w][16 + lane], og = zb[w][24 + lane];
            float c = sigf(fg) * cs[w][lane] + sigf(ig) * tanhf(gg);
            float h = sigf(og) * tanhf(c);
            cs[w][lane] = c; hs[w][lane] = h;
            g_enc[((size_t)b * 16 + t) * 16000 + n * 8 + lane] = h;
        }
        __syncwarp();
    }
}

// ---------------- K4: QKV projection ----------------
__global__ void __launch_bounds__(256) k_qkv(const float* __restrict__ Wq,
                                             const float* __restrict__ Wk,
                                             const float* __restrict__ Wv) {
    __shared__ float As[10][128];
    __shared__ float Bs[10][96];
    int tid = threadIdx.x; int tx = tid & 15, ty = tid >> 4;
    int k0 = blockIdx.x * 250;
    float acc[8][6];
#pragma unroll
    for (int i = 0; i < 8; i++)
#pragma unroll
        for (int j = 0; j < 6; j++) acc[i][j] = 0.f;
    for (int kk0 = 0; kk0 < 250; kk0 += 10) {
        for (int idx = tid; idx < 1280; idx += 256) {
            int r = idx / 10, k = idx % 10;
            As[k][r] = g_enc[(size_t)r * 16000 + k0 + kk0 + k];
        }
        for (int idx = tid; idx < 960; idx += 256) {
            int k = idx / 96, c = idx % 96;
            int wcol = c & 31; int sel = c >> 5;
            const float* W = (sel == 0) ? Wq : ((sel == 1) ? Wk : Wv);
            Bs[k][c] = W[(size_t)(k0 + kk0 + k) * 32 + wcol];
        }
        __syncthreads();
#pragma unroll
        for (int k = 0; k < 10; k++) {
            float a[8], bv[6];
#pragma unroll
            for (int i = 0; i < 8; i++) a[i] = As[k][ty * 8 + i];
#pragma unroll
            for (int j = 0; j < 6; j++) bv[j] = Bs[k][tx * 6 + j];
#pragma unroll
            for (int i = 0; i < 8; i++)
#pragma unroll
                for (int j = 0; j < 6; j++) acc[i][j] += a[i] * bv[j];
        }
        __syncthreads();
    }
#pragma unroll
    for (int i = 0; i < 8; i++)
#pragma unroll
        for (int j = 0; j < 6; j++)
            atomicAdd(&g_qkv[(ty * 8 + i) * 96 + tx * 6 + j], acc[i][j]);
}

// ---------------- K5: causal attention ----------------
__global__ void k_attn() {
    int bh = blockIdx.x; int b = bh >> 2, h = bh & 3;
    __shared__ float kk[16][8], vv[16][8];
    int lane = threadIdx.x;
    for (int idx = lane; idx < 128; idx += 32) {
        int t = idx >> 3, d = idx & 7;
        kk[t][d] = g_qkv[(b * 16 + t) * 96 + 32 + h * 8 + d];
        vv[t][d] = g_qkv[(b * 16 + t) * 96 + 64 + h * 8 + d];
    }
    __syncwarp();
    if (lane < 16) {
        int i = lane;
        float qv[8];
#pragma unroll
        for (int d = 0; d < 8; d++) qv[d] = g_qkv[(b * 16 + i) * 96 + h * 8 + d];
        float sc[16]; float mx = -1e30f;
#pragma unroll
        for (int j = 0; j < 16; j++) {
            if (j <= i) {
                float s = 0.f;
#pragma unroll
                for (int d = 0; d < 8; d++) s += qv[d] * kk[j][d];
                s *= 0.35355339059327373f;
                sc[j] = s; mx = fmaxf(mx, s);
            } else sc[j] = -1e30f;
        }
        float den = 0.f, p[16];
#pragma unroll
        for (int j = 0; j < 16; j++) {
            p[j] = (j <= i) ? expf(sc[j] - mx) : 0.f;
            den += p[j];
        }
        float rden = 1.f / den;
#pragma unroll
        for (int d = 0; d < 8; d++) {
            float c = 0.f;
#pragma unroll
            for (int j = 0; j < 16; j++) c += p[j] * vv[j][d];
            g_ctx[(b * 16 + i) * 32 + h * 8 + d] = c * rden;
        }
    }
}

// ---------------- K6: O-proj + residual + LN2, scatter to Xf ----------------
__global__ void __launch_bounds__(256) k_oproj(const float* __restrict__ Wo,
                                               const float* __restrict__ gg,
                                               const float* __restrict__ bb) {
    int bt = blockIdx.x; int b = bt >> 4, t = bt & 15;
    int tid = threadIdx.x;
    __shared__ float cs2[32];
    if (tid < 32) cs2[tid] = g_ctx[bt * 32 + tid];
    __syncthreads();
    float* er = g_enc + (size_t)bt * 16000;
    float s = 0.f, q = 0.f;
    for (int d = tid; d < 16000; d += 256) {
        float y = er[d];
#pragma unroll
        for (int j = 0; j < 32; j++) y += cs2[j] * Wo[(size_t)j * 16000 + d];
        er[d] = y; s += y; q += y * y;
    }
    __shared__ float rs[256], rq[256];
    rs[tid] = s; rq[tid] = q; __syncthreads();
    for (int off = 128; off > 0; off >>= 1) {
        if (tid < off) { rs[tid] += rs[tid + off]; rq[tid] += rq[tid + off]; }
        __syncthreads();
    }
    float mu = rs[0] * (1.f / 16000.f);
    float var = rq[0] * (1.f / 16000.f) - mu * mu;
    float inv = rsqrtf(var + 1e-5f);
    for (int d = tid; d < 16000; d += 256) {
        float y = er[d];
        float v = (y - mu) * inv * gg[d] + bb[d];
        int n = d >> 3, j = d & 7;
        g_Xf[((size_t)b * 2000 + n) * 128 + t * 8 + j] = v;
    }
}

// ---------------- K7a: theta1 -> blocked B1 ----------------
__global__ void __launch_bounds__(128) k_theta1(const float* __restrict__ th) {
    int m0 = blockIdx.x * 16; int b = blockIdx.y;
    __shared__ float As[16][128];
    int tid = threadIdx.x;
    for (int idx = tid; idx < 2048; idx += 128) {
        int mm = idx >> 7, e = idx & 127;
        As[mm][e] = g_Xf[((size_t)b * 2000 + m0 + mm) * 128 + e];
    }
    __syncthreads();
    float acc[16];
#pragma unroll
    for (int mm = 0; mm < 16; mm++) acc[mm] = 0.f;
    int d = tid;
    for (int e = 0; e < 128; e++) {
        float tv = th[e * 128 + d];
#pragma unroll
        for (int mm = 0; mm < 16; mm++) acc[mm] += As[mm][e] * tv;
    }
    int c = b * 128 + d;
#pragma unroll
    for (int mm = 0; mm < 16; mm++)
        g_B1b[fblk(c, m0 + mm)] = __float2bfloat16(acc[mm]);
}

// ---------------- K7b: theta2: F1 -> X2 (blocked in/out) ----------------
__global__ void __launch_bounds__(128) k_theta2(const float* __restrict__ th) {
    int n0 = blockIdx.x * 16; int b = blockIdx.y; int z = blockIdx.z;
    const __nv_bfloat16* F = g_F1b + (size_t)z * FZ;
    __nv_bfloat16* X = g_X2b + (size_t)z * FZ;
    __shared__ float As[16][128];     // As[nn][d]
    int tid = threadIdx.x;
    for (int idx = tid; idx < 2048; idx += 128) {
        int d = idx >> 4, nn = idx & 15;
        As[nn][d] = __bfloat162float(F[fblk(b * 128 + d, n0 + nn)]);
    }
    __syncthreads();
    float acc[16];
#pragma unroll
    for (int nn = 0; nn < 16; nn++) acc[nn] = 0.f;
    int e = tid;
    for (int d = 0; d < 128; d++) {
        float tv = th[d * 128 + e];
#pragma unroll
        for (int nn = 0; nn < 16; nn++) acc[nn] += As[nn][d] * tv;
    }
    int c = b * 128 + e;
#pragma unroll
    for (int nn = 0; nn < 16; nn++)
        X[fblk(c, n0 + nn)] = __float2bfloat16(acc[nn]);
}

// ---------------- K8: bf16 HMMA GEMM with bulk-copy loads ----------------
// Blocked A [kc][2048 rows][64k], blocked B [kc][1024 rows][64k]; C [c][m].
// bSel: 0=B1b(shared) 1=T1b 2=X2b 3=T2b ; oSel: 0=hyp(atomic) 1=T1b 2=F1b 3=T2b
#define STG 32768               // per-stage: A 16KB + B 16KB
#define NST 3
__global__ void __launch_bounds__(256, 2) k_mmagemm(
        const __nv_bfloat16* __restrict__ Abase, int bSel, int oSel,
        const float* __restrict__ rowscale, const float* __restrict__ parv, int leaky) {
    extern __shared__ char dsm[];
    char* sm = (char*)(((uintptr_t)dsm + 1023) & ~(uintptr_t)1023);
    uint32_t sb = s2u(sm);
    uint32_t barb = sb + NST * STG;             // 3 mbarriers, 8B each
    int tid = threadIdx.x, wid = tid >> 5, lane = tid & 31;
    int z = blockIdx.z;
    int m0 = blockIdx.y * 128, n0 = blockIdx.x * 128;

    const __nv_bfloat16* Ap = Abase + (size_t)z * WZ;
    size_t bz = (size_t)z * FZ;
    const __nv_bfloat16* Bp;
    if (bSel == 0)      Bp = g_B1b;
    else if (bSel == 1) Bp = g_T1b + bz;
    else if (bSel == 2) Bp = g_X2b + bz;
    else                Bp = g_T2b + bz;

    if (tid == 0) {
        MBAR_INIT(barb, 1u); MBAR_INIT(barb + 8, 1u); MBAR_INIT(barb + 16, 1u);
    }
    __syncthreads();

    // issue one chunk: A(128 rows from m0) + B(128 rows from n0), 16KB each
    auto issue = [&](int ck, int buf) {
        uint32_t bar = barb + buf * 8;
        MBAR_EXPECT(bar, 32768u);
        bulk_g2s(sb + buf * STG,         Ap + (((size_t)(ck * 2048 + m0)) << 6), 16384u, bar);
        bulk_g2s(sb + buf * STG + 16384, Bp + (((size_t)(ck * 1024 + n0)) << 6), 16384u, bar);
    };
    if (tid == 0) { issue(0, 0); issue(1, 1); }

    float acc[4][4][4];
#pragma unroll
    for (int i = 0; i < 4; i++)
#pragma unroll
        for (int j = 0; j < 4; j++)
#pragma unroll
            for (int r = 0; r < 4; r++) acc[i][j][r] = 0.f;

    int wm = (wid & 1) * 64;        // warp m offset (2 x 64)
    int wn = (wid >> 1) * 32;       // warp n offset (4 x 32)
    uint32_t rsel = (lane & 15);
    uint32_t csel = ((lane >> 4) & 1) * 16;
    uint32_t swz = (rsel & 7) << 4;

    int buf = 0;
    for (int ck = 0; ck < KC; ck++) {
        MBAR_WAIT(barb + buf * 8, (uint32_t)((ck / NST) & 1));
        uint32_t base = sb + buf * STG;
#pragma unroll
        for (int sub = 0; sub < 4; sub++) {
            uint32_t cb = (csel + sub * 32) ^ swz;
            uint32_t ah[4][4], bh[4][2];
#pragma unroll
            for (int mi = 0; mi < 4; mi++)
                ldmat4(ah[mi], base + (wm + mi * 16 + rsel) * 128 + cb);
#pragma unroll
            for (int nj = 0; nj < 2; nj++) {
                uint32_t r4[4];
                ldmat4(r4, base + 16384 + (wn + nj * 16 + rsel) * 128 + cb);
                bh[nj * 2][0] = r4[0]; bh[nj * 2][1] = r4[2];
                bh[nj * 2 + 1][0] = r4[1]; bh[nj * 2 + 1][1] = r4[3];
            }
#pragma unroll
            for (int mi = 0; mi < 4; mi++)
#pragma unroll
                for (int ni = 0; ni < 4; ni++)
                    mma16816(acc[mi][ni], ah[mi], bh[ni]);
        }
        __syncthreads();                       // all warps done reading buf
        if (tid == 0 && ck + 2 < KC) issue(ck + 2, (buf + 2 >= NST) ? buf + 2 - NST : buf + 2);
        buf = (buf + 1 == NST) ? 0 : buf + 1;
    }
    __syncthreads();

    // ---- epilogue: scale / leaky / alpha, two 64-n passes through 32KB SMEM stage ----
    float alpha = parv ? parv[z] : 1.f;
    float* st = (float*)sm;
    int mlo0 = wm + (lane >> 2);
    float rsv[8];
#pragma unroll
    for (int mi = 0; mi < 4; mi++) {
        int mlo = mlo0 + mi * 16;
        rsv[mi * 2]     = rowscale ? ((m0 + mlo < 2000) ? rowscale[m0 + mlo] : 0.f) : 1.f;
        rsv[mi * 2 + 1] = rowscale ? ((m0 + mlo + 8 < 2000) ? rowscale[m0 + mlo + 8] : 0.f) : 1.f;
    }
    __nv_bfloat16* C = nullptr;
    if (oSel == 1)      C = g_T1b + bz;
    else if (oSel == 2) C = g_F1b + bz;
    else if (oSel == 3) C = g_T2b + bz;

    for (int p = 0; p < 2; p++) {
        if ((wn >> 6) == p) {
            int wnl = wn - p * 64;
#pragma unroll
            for (int mi = 0; mi < 4; mi++) {
                int mlo = mlo0 + mi * 16;
#pragma unroll
                for (int ni = 0; ni < 4; ni++) {
                    int nl = wnl + ni * 8 + (lane & 3) * 2;
#pragma unroll
                    for (int r = 0; r < 4; r++) {
                        float v = acc[mi][ni][r];
                        int ml = (r < 2) ? mlo : (mlo + 8);
                        v *= rsv[mi * 2 + (r < 2 ? 0 : 1)];
                        if (leaky) v = (v > 0.f) ? v : SLOPE * v;
                        v *= alpha;
                        st[(nl + (r & 1)) * 128 + ml] = v;
                    }
                }
            }
        }
        __syncthreads();
        if (oSel == 0) {
            for (int idx = tid; idx < 8192; idx += 256) {
                int nl = idx >> 7, ml = idx & 127;
                if (m0 + ml < 2000)
                    atomicAdd(&g_hyp[(size_t)(n0 + p * 64 + nl) * 2000 + m0 + ml], st[idx]);
            }
        } else {
            for (int idx = tid; idx < 8192; idx += 256) {
                int nl = idx >> 7, ml = idx & 127;
                C[fblk(n0 + p * 64 + nl, m0 + ml)] = __float2bfloat16(st[idx]);
            }
        }
        __syncthreads();
    }
}

// ---------------- K9: final MLP ----------------
__global__ void __launch_bounds__(256) k_mlp(
                      const float* __restrict__ w1, const float* __restrict__ b1m,
                      const float* __restrict__ w2, const float* __restrict__ b2m,
                      float* __restrict__ out) {
    __shared__ float sw1[256], sb1[16], sw2[16], sb2;
    int tid = threadIdx.x;
    sw1[tid] = w1[tid];
    if (tid < 16) { sb1[tid] = b1m[tid]; sw2[tid] = w2[tid]; }
    if (tid == 0) sb2 = b2m[0];
    __syncthreads();
    int idx = blockIdx.x * 256 + tid;
    int b = idx / 32000; int rem = idx - b * 32000;
    int n = rem >> 4; int t = rem & 15;
    float cat[16];
    const float* xf = g_Xf + ((size_t)b * 2000 + n) * 128 + t * 8;
#pragma unroll
    for (int j = 0; j < 8; j++) {
        cat[j] = xf[j];
        cat[8 + j] = g_hyp[(size_t)(b * 128 + t * 8 + j) * 2000 + n];
    }
    float acc = sb2;
#pragma unroll
    for (int i = 0; i < 16; i++) {
        float mi = sb1[i];
#pragma unroll
        for (int j = 0; j < 16; j++) mi += cat[j] * sw1[j * 16 + i];
        mi = fmaxf(mi, 0.f);
        acc += mi * sw2[i];
    }
    out[idx] = acc;
}

// ---------------- launch ----------------
#define GSMEM (NST * STG + 64 + 1024)   // stages + mbarriers + align slack = 99392

extern "C" void kernel_launch(void* const* d_in, const int* in_sizes, int n_in,
                              void* d_out, int out_size) {
    const float* inp  = (const float*)d_in[0];
    const float* embW = (const float*)d_in[1];
    const float* embB = (const float*)d_in[2];
    const float* W1   = (const float*)d_in[3];
    const float* U1   = (const float*)d_in[4];
    const float* b1   = (const float*)d_in[5];
    const float* ln1g = (const float*)d_in[6];
    const float* ln1b = (const float*)d_in[7];
    const float* W2   = (const float*)d_in[8];
    const float* U2   = (const float*)d_in[9];
    const float* b2   = (const float*)d_in[10];
    const float* Wq   = (const float*)d_in[11];
    const float* Wk   = (const float*)d_in[12];
    const float* Wv   = (const float*)d_in[13];
    const float* Wo   = (const float*)d_in[14];
    const float* ln2g = (const float*)d_in[15];
    const float* ln2b = (const float*)d_in[16];
    const float* par  = (const float*)d_in[17];
    const float* th1  = (const float*)d_in[18];
    const float* dg1  = (const float*)d_in[19];
    const float* th2  = (const float*)d_in[20];
    const float* dg2  = (const float*)d_in[21];
    const float* m1W  = (const float*)d_in[22];
    const float* m1b  = (const float*)d_in[23];
    const float* m2W  = (const float*)d_in[24];
    const float* m2b  = (const float*)d_in[25];
    const float* wav  = (const float*)d_in[26];
    const float* winv = (const float*)d_in[27];
    float* out = (float*)d_out;

    cudaFuncSetAttribute(k_mmagemm, cudaFuncAttributeMaxDynamicSharedMemorySize, GSMEM);

    __nv_bfloat16* wiB;  cudaGetSymbolAddress((void**)&wiB,  g_wiB);
    __nv_bfloat16* wavB; cudaGetSymbolAddress((void**)&wavB, g_wavB);

    k_zero<<<2000, 256>>>();
    k_cvtB<<<31250, 256>>>(wav, winv);
    k_lstm1<<<4000, 128>>>(inp, embW, embB, W1, U1, b1);
    k_ln1<<<128, 1024>>>(ln1g, ln1b);
    k_lstm2<<<4000, 128>>>(W2, U2, b2);
    k_qkv<<<64, 256>>>(Wq, Wk, Wv);
    k_attn<<<32, 32>>>();
    k_oproj<<<128, 256>>>(Wo, ln2g, ln2b);

    // hypergraph, layer 1
    k_theta1<<<dim3(125, 8), 128>>>(th1);                                          // B1 = (Xf@th1)^T
    k_mmagemm<<<dim3(8, 16, 4), 256, GSMEM>>>(wiB,  0, 1, dg1, nullptr, 0);        // T1 = diag1*(Winv@X1)
    k_mmagemm<<<dim3(8, 16, 4), 256, GSMEM>>>(wavB, 1, 2, nullptr, nullptr, 1);    // F1 = leaky(W@T1)
    // layer 2
    k_theta2<<<dim3(125, 8, 4), 128>>>(th2);                                       // X2 = F1@th2
    k_mmagemm<<<dim3(8, 16, 4), 256, GSMEM>>>(wiB,  2, 3, dg2, nullptr, 0);        // T2 = diag2*(Winv@X2)
    k_mmagemm<<<dim3(8, 16, 4), 256, GSMEM>>>(wavB, 3, 0, nullptr, par, 1);        // hyp += par*leaky(W@T2)

    k_mlp<<<1000, 256>>>(m1W, m1b, m2W, m2b, out);
}

// round 17
// speedup vs baseline: 1.1838x; 1.0472x over previous
#include <cuda_runtime.h>
#include <cuda_bf16.h>
#include <math.h>
#include <stdint.h>

// ---------------- constants ----------------
#define SLOPE 0.1f
#define KC 32                       // 64-wide K chunks (2048 padded K)
#define WZ (KC * 2048 * 64)         // wavelet blocked elems per z  (4,194,304)
#define FZ (KC * 1024 * 64)         // feature blocked elems per z  (2,097,152)

// ---------------- scratch (device globals; no allocation) ----------------
__device__ float g_h1[16000 * 16 * 16];      // [b*N+n][t][16]
__device__ float g_o [16000 * 16 * 16];      // LN1 out, same layout
__device__ float g_enc[128 * 16000];         // [b*16+t][DM]
__device__ float g_qkv[128 * 96];            // [bt][96] (q|k|v)
__device__ float g_ctx[128 * 32];            // [bt][32]
__device__ float g_Xf [16000 * 128];         // [b*N+n][128]
__device__ float g_hyp4[4 * 2000 * 1024];    // per-z [node][c=(b*128+d)], plain stores

// blocked + SW128-swizzled bf16 operands: [kc][row][64 k], 16KB-contiguous chunks
__device__ __align__(16) __nv_bfloat16 g_wavB[4 * WZ], g_wiB[4 * WZ];
__device__ __align__(16) __nv_bfloat16 g_B1b[FZ];
__device__ __align__(16) __nv_bfloat16 g_T1b[4 * FZ];
__device__ __align__(16) __nv_bfloat16 g_F1b[4 * FZ];
__device__ __align__(16) __nv_bfloat16 g_X2b[4 * FZ];
__device__ __align__(16) __nv_bfloat16 g_T2b[4 * FZ];

__device__ __forceinline__ float sigf(float x) { return 1.f / (1.f + expf(-x)); }

__device__ __forceinline__ uint32_t s2u(const void* p) {
    uint32_t a;
    asm("{ .reg .u64 t; cvta.to.shared.u64 t, %1; cvt.u32.u64 %0, t; }" : "=r"(a) : "l"(p));
    return a;
}
// blocked elem index: wavelet matrices (2048 rows per kc)
__device__ __forceinline__ size_t wblk(int n, int k) {
    int kc = k >> 6;
    int kb = ((k & 63) * 2) ^ ((n & 7) << 4);     // swizzled byte-in-row
    return (((size_t)(kc * 2048 + n)) << 6) + (kb >> 1);
}
// blocked elem index: feature matrices (1024 rows per kc)
__device__ __forceinline__ size_t fblk(int c, int k) {
    int kc = k >> 6;
    int kb = ((k & 63) * 2) ^ ((c & 7) << 4);
    return (((size_t)(kc * 1024 + c)) << 6) + (kb >> 1);
}
__device__ __forceinline__ void ldmat4(uint32_t* r, uint32_t addr) {
    asm volatile("ldmatrix.sync.aligned.m8n8.x4.shared.b16 {%0,%1,%2,%3}, [%4];"
                 : "=r"(r[0]), "=r"(r[1]), "=r"(r[2]), "=r"(r[3]) : "r"(addr));
}
__device__ __forceinline__ void mma16816(float* c, const uint32_t* a, const uint32_t* b) {
    asm volatile("mma.sync.aligned.m16n8k16.row.col.f32.bf16.bf16.f32 "
                 "{%0,%1,%2,%3}, {%4,%5,%6,%7}, {%8,%9}, {%0,%1,%2,%3};"
                 : "+f"(c[0]), "+f"(c[1]), "+f"(c[2]), "+f"(c[3])
                 : "r"(a[0]), "r"(a[1]), "r"(a[2]), "r"(a[3]), "r"(b[0]), "r"(b[1]));
}
#define MBAR_INIT(addr, cnt) \
    asm volatile("mbarrier.init.shared.b64 [%0], %1;" :: "r"(addr), "r"(cnt) : "memory")
#define MBAR_EXPECT(addr, tx) \
    asm volatile("mbarrier.arrive.expect_tx.shared.b64 _, [%0], %1;" :: "r"(addr), "r"(tx) : "memory")
#define MBAR_WAIT(addr, parity) do { \
    uint32_t _m = (addr), _p = (parity), _d; \
    asm volatile("{\n\t.reg .pred p;\n\t" \
        "mbarrier.try_wait.parity.acquire.cta.shared::cta.b64 p, [%1], %2;\n\t" \
        "selp.b32 %0, 1, 0, p;\n\t}" : "=r"(_d) : "r"(_m), "r"(_p) : "memory"); \
    if (!_d) { \
        asm volatile("{\n\t.reg .pred P1;\n\t" \
            "WL%=:\n\t" \
            "mbarrier.try_wait.parity.acquire.cta.shared::cta.b64 P1, [%0], %1, 0x989680;\n\t" \
            "@P1 bra.uni WD%=;\n\t" \
            "bra.uni WL%=;\n\t" \
            "WD%=:\n\t}" :: "r"(_m), "r"(_p) : "memory"); \
    } \
} while (0)
__device__ __forceinline__ void bulk_g2s(uint32_t dst, const void* src, uint32_t bytes,
                                         uint32_t mbar) {
    asm volatile("cp.async.bulk.shared::cta.global.mbarrier::complete_tx::bytes "
                 "[%0], [%1], %2, [%3];"
                 :: "r"(dst), "l"(src), "r"(bytes), "r"(mbar) : "memory");
}

// ---------------- K0: zero qkv accumulator (tiny) ----------------
__global__ void k_zero() {
    int i = blockIdx.x * blockDim.x + threadIdx.x;
    if (i < 3072) *(float4*)&g_qkv[i * 4] = make_float4(0.f, 0.f, 0.f, 0.f);
}

// ---------------- K-cvtB: wavelets fp32 -> blocked swizzled bf16 ----------------
__global__ void __launch_bounds__(256) k_cvtB(const float* __restrict__ wav,
                                              const float* __restrict__ winv) {
    long long idx = (long long)blockIdx.x * 256 + threadIdx.x;   // (z, n, kpair)
    if (idx >= 8000000LL) return;
    int kp = (int)(idx % 1000);
    int rest = (int)(idx / 1000);
    int n = rest % 2000;
    int z = rest / 2000;
    int k = kp * 2;
    size_t src = (size_t)z * 4000000 + (size_t)n * 2000 + k;
    float2 w = *(const float2*)&wav[src];
    float2 v = *(const float2*)&winv[src];
    size_t dst = (size_t)z * WZ + wblk(n, k);
    *(__nv_bfloat162*)&g_wavB[dst] = __floats2bfloat162_rn(w.x, w.y);
    *(__nv_bfloat162*)&g_wiB[dst]  = __floats2bfloat162_rn(v.x, v.y);
}

// ---------------- K1: embedding + LSTM1 (warp per (b,n) row) ----------------
__global__ void __launch_bounds__(128) k_lstm1(
                        const float* __restrict__ inp,
                        const float* __restrict__ embW, const float* __restrict__ embB,
                        const float* __restrict__ W1, const float* __restrict__ U1,
                        const float* __restrict__ b1) {
    __shared__ float sW[16 * 64], sU[16 * 64], sb[64], sEw[10 * 16], sEb[16];
    __shared__ float xs[4][16][16];
    __shared__ float zb[4][64], hs[4][16], cs[4][16];
    int tid = threadIdx.x;
    for (int i = tid; i < 1024; i += 128) { sW[i] = W1[i]; sU[i] = U1[i]; }
    for (int i = tid; i < 160; i += 128) sEw[i] = embW[i];
    if (tid < 64) sb[tid] = b1[tid];
    if (tid < 16) sEb[tid] = embB[tid];
    __syncthreads();
    int w = tid >> 5, lane = tid & 31;
    int gw = blockIdx.x * 4 + w;
    const float* irow = inp + (size_t)gw * 160;
    if (lane < 16) {
        for (int t = 0; t < 16; t++) {
            float acc = sEb[lane];
#pragma unroll
            for (int f = 0; f < 10; f++) acc += irow[t * 10 + f] * sEw[f * 16 + lane];
            xs[w][t][lane] = acc;
        }
        hs[w][lane] = 0.f; cs[w][lane] = 0.f;
    }
    __syncwarp();
    float* outr = g_h1 + (size_t)gw * 256;
    for (int t = 0; t < 16; t++) {
        int j1 = lane, j2 = lane + 32;
        float z1 = sb[j1], z2 = sb[j2];
#pragma unroll
        for (int e = 0; e < 16; e++) {
            float x = xs[w][t][e];
            z1 += x * sW[e * 64 + j1]; z2 += x * sW[e * 64 + j2];
        }
#pragma unroll
        for (int k = 0; k < 16; k++) {
            float hk = hs[w][k];
            z1 += hk * sU[k * 64 + j1]; z2 += hk * sU[k * 64 + j2];
        }
        zb[w][j1] = z1; zb[w][j2] = z2;
        __syncwarp();
        if (lane < 16) {
            float ig = zb[w][lane], fg = zb[w][16 + lane];
            float gg = zb[w][32 + lane], og = zb[w][48 + lane];
            float c = sigf(fg) * cs[w][lane] + sigf(ig) * tanhf(gg);
            float h = sigf(og) * tanhf(c);
            cs[w][lane] = c; hs[w][lane] = h;
            outr[t * 16 + lane] = h;
        }
        __syncwarp();
    }
}

// ---------------- K2: LayerNorm over N*H1=32000 per (b,t) ----------------
__global__ void __launch_bounds__(1024) k_ln1(const float* __restrict__ gg,
                                              const float* __restrict__ bb) {
    int bt = blockIdx.x; int b = bt >> 4, t = bt & 15;
    int tid = threadIdx.x;
    size_t base = (size_t)b * 512000 + t * 16;
    float s = 0.f, q = 0.f;
    for (int d = tid; d < 32000; d += 1024) {
        int n = d >> 4, j = d & 15;
        float v = g_h1[base + (size_t)n * 256 + j];
        s += v; q += v * v;
    }
    __shared__ float rs[1024], rq[1024];
    rs[tid] = s; rq[tid] = q; __syncthreads();
    for (int off = 512; off > 0; off >>= 1) {
        if (tid < off) { rs[tid] += rs[tid + off]; rq[tid] += rq[tid + off]; }
        __syncthreads();
    }
    float mu = rs[0] * (1.f / 32000.f);
    float var = rq[0] * (1.f / 32000.f) - mu * mu;
    float inv = rsqrtf(var + 1e-5f);
    for (int d = tid; d < 32000; d += 1024) {
        int n = d >> 4, j = d & 15;
        size_t a = base + (size_t)n * 256 + j;
        g_o[a] = (g_h1[a] - mu) * inv * gg[d] + bb[d];
    }
}

// ---------------- K3: LSTM2 (warp per row) ----------------
__global__ void __launch_bounds__(128) k_lstm2(
                        const float* __restrict__ W2, const float* __restrict__ U2,
                        const float* __restrict__ b2) {
    __shared__ float sW[16 * 32], sU[8 * 32], sb[32];
    __shared__ float xs[4][16][16];
    __shared__ float zb[4][32], hs[4][8], cs[4][8];
    int tid = threadIdx.x;
    for (int i = tid; i < 512; i += 128) sW[i] = W2[i];
    for (int i = tid; i < 256; i += 128) sU[i] = U2[i];
    if (tid < 32) sb[tid] = b2[tid];
    __syncthreads();
    int w = tid >> 5, lane = tid & 31;
    int gw = blockIdx.x * 4 + w;
    for (int idx = lane; idx < 256; idx += 32)
        xs[w][idx >> 4][idx & 15] = g_o[(size_t)gw * 256 + idx];
    if (lane < 8) { hs[w][lane] = 0.f; cs[w][lane] = 0.f; }
    __syncwarp();
    int b = gw / 2000, n = gw - b * 2000;
    for (int t = 0; t < 16; t++) {
        float z = sb[lane];
#pragma unroll
        for (int e = 0; e < 16; e++) z += xs[w][t][e] * sW[e * 32 + lane];
#pragma unroll
        for (int k = 0; k < 8; k++) z += hs[w][k] * sU[k * 32 + lane];
        zb[w][lane] = z;
        __syncwarp();
        if (lane < 8) {
            float ig = zb[w][lane], fg = zb[w][8 + lane];
            float gg = zb[w][16 + lane], og = zb[w][24 + lane];
            float c = sigf(fg) * cs[w][lane] + sigf(ig) * tanhf(gg);
            float h = sigf(og) * tanhf(c);
            cs[w][lane] = c; hs[w][lane] = h;
            g_enc[((size_t)b * 16 + t) * 16000 + n * 8 + lane] = h;
        }
        __syncwarp();
    }
}

// ---------------- K4: QKV projection (160-way split-K) ----------------
__global__ void __launch_bounds__(256) k_qkv(const float* __restrict__ Wq,
                                             const float* __restrict__ Wk,
                                             const float* __restrict__ Wv) {
    __shared__ float As[10][128];
    __shared__ float Bs[10][96];
    int tid = threadIdx.x; int tx = tid & 15, ty = tid >> 4;
    int k0 = blockIdx.x * 100;
    float acc[8][6];
#pragma unroll
    for (int i = 0; i < 8; i++)
#pragma unroll
        for (int j = 0; j < 6; j++) acc[i][j] = 0.f;
    for (int kk0 = 0; kk0 < 100; kk0 += 10) {
        for (int idx = tid; idx < 1280; idx += 256) {
            int r = idx / 10, k = idx % 10;
            As[k][r] = g_enc[(size_t)r * 16000 + k0 + kk0 + k];
        }
        for (int idx = tid; idx < 960; idx += 256) {
            int k = idx / 96, c = idx % 96;
            int wcol = c & 31; int sel = c >> 5;
            const float* W = (sel == 0) ? Wq : ((sel == 1) ? Wk : Wv);
            Bs[k][c] = W[(size_t)(k0 + kk0 + k) * 32 + wcol];
        }
        __syncthreads();
#pragma unroll
        for (int k = 0; k < 10; k++) {
            float a[8], bv[6];
#pragma unroll
            for (int i = 0; i < 8; i++) a[i] = As[k][ty * 8 + i];
#pragma unroll
            for (int j = 0; j < 6; j++) bv[j] = Bs[k][tx * 6 + j];
#pragma unroll
            for (int i = 0; i < 8; i++)
#pragma unroll
                for (int j = 0; j < 6; j++) acc[i][j] += a[i] * bv[j];
        }
        __syncthreads();
    }
#pragma unroll
    for (int i = 0; i < 8; i++)
#pragma unroll
        for (int j = 0; j < 6; j++)
            atomicAdd(&g_qkv[(ty * 8 + i) * 96 + tx * 6 + j], acc[i][j]);
}

// ---------------- K5: causal attention ----------------
__global__ void k_attn() {
    int bh = blockIdx.x; int b = bh >> 2, h = bh & 3;
    __shared__ float kk[16][8], vv[16][8];
    int lane = threadIdx.x;
    for (int idx = lane; idx < 128; idx += 32) {
        int t = idx >> 3, d = idx & 7;
        kk[t][d] = g_qkv[(b * 16 + t) * 96 + 32 + h * 8 + d];
        vv[t][d] = g_qkv[(b * 16 + t) * 96 + 64 + h * 8 + d];
    }
    __syncwarp();
    if (lane < 16) {
        int i = lane;
        float qv[8];
#pragma unroll
        for (int d = 0; d < 8; d++) qv[d] = g_qkv[(b * 16 + i) * 96 + h * 8 + d];
        float sc[16]; float mx = -1e30f;
#pragma unroll
        for (int j = 0; j < 16; j++) {
            if (j <= i) {
                float s = 0.f;
#pragma unroll
                for (int d = 0; d < 8; d++) s += qv[d] * kk[j][d];
                s *= 0.35355339059327373f;
                sc[j] = s; mx = fmaxf(mx, s);
            } else sc[j] = -1e30f;
        }
        float den = 0.f, p[16];
#pragma unroll
        for (int j = 0; j < 16; j++) {
            p[j] = (j <= i) ? expf(sc[j] - mx) : 0.f;
            den += p[j];
        }
        float rden = 1.f / den;
#pragma unroll
        for (int d = 0; d < 8; d++) {
            float c = 0.f;
#pragma unroll
            for (int j = 0; j < 16; j++) c += p[j] * vv[j][d];
            g_ctx[(b * 16 + i) * 32 + h * 8 + d] = c * rden;
        }
    }
}

// ---------------- K6: O-proj + residual + LN2, scatter to Xf ----------------
__global__ void __launch_bounds__(256) k_oproj(const float* __restrict__ Wo,
                                               const float* __restrict__ gg,
                                               const float* __restrict__ bb) {
    int bt = blockIdx.x; int b = bt >> 4, t = bt & 15;
    int tid = threadIdx.x;
    __shared__ float cs2[32];
    if (tid < 32) cs2[tid] = g_ctx[bt * 32 + tid];
    __syncthreads();
    float* er = g_enc + (size_t)bt * 16000;
    float s = 0.f, q = 0.f;
    for (int d = tid; d < 16000; d += 256) {
        float y = er[d];
#pragma unroll
        for (int j = 0; j < 32; j++) y += cs2[j] * Wo[(size_t)j * 16000 + d];
        er[d] = y; s += y; q += y * y;
    }
    __shared__ float rs[256], rq[256];
    rs[tid] = s; rq[tid] = q; __syncthreads();
    for (int off = 128; off > 0; off >>= 1) {
        if (tid < off) { rs[tid] += rs[tid + off]; rq[tid] += rq[tid + off]; }
        __syncthreads();
    }
    float mu = rs[0] * (1.f / 16000.f);
    float var = rq[0] * (1.f / 16000.f) - mu * mu;
    float inv = rsqrtf(var + 1e-5f);
    for (int d = tid; d < 16000; d += 256) {
        float y = er[d];
        float v = (y - mu) * inv * gg[d] + bb[d];
        int n = d >> 3, j = d & 7;
        g_Xf[((size_t)b * 2000 + n) * 128 + t * 8 + j] = v;
    }
}

// ---------------- K7a: theta1 -> blocked B1 ----------------
__global__ void __launch_bounds__(128) k_theta1(const float* __restrict__ th) {
    int m0 = blockIdx.x * 16; int b = blockIdx.y;
    __shared__ float As[16][128];
    int tid = threadIdx.x;
    for (int idx = tid; idx < 2048; idx += 128) {
        int mm = idx >> 7, e = idx & 127;
        As[mm][e] = g_Xf[((size_t)b * 2000 + m0 + mm) * 128 + e];
    }
    __syncthreads();
    float acc[16];
#pragma unroll
    for (int mm = 0; mm < 16; mm++) acc[mm] = 0.f;
    int d = tid;
    for (int e = 0; e < 128; e++) {
        float tv = th[e * 128 + d];
#pragma unroll
        for (int mm = 0; mm < 16; mm++) acc[mm] += As[mm][e] * tv;
    }
    int c = b * 128 + d;
#pragma unroll
    for (int mm = 0; mm < 16; mm++)
        g_B1b[fblk(c, m0 + mm)] = __float2bfloat16(acc[mm]);
}

// ---------------- K7b: theta2: F1 -> X2 (blocked in/out) ----------------
__global__ void __launch_bounds__(128) k_theta2(const float* __restrict__ th) {
    int n0 = blockIdx.x * 16; int b = blockIdx.y; int z = blockIdx.z;
    const __nv_bfloat16* F = g_F1b + (size_t)z * FZ;
    __nv_bfloat16* X = g_X2b + (size_t)z * FZ;
    __shared__ float As[16][128];     // As[nn][d]
    int tid = threadIdx.x;
    for (int idx = tid; idx < 2048; idx += 128) {
        int d = idx >> 4, nn = idx & 15;
        As[nn][d] = __bfloat162float(F[fblk(b * 128 + d, n0 + nn)]);
    }
    __syncthreads();
    float acc[16];
#pragma unroll
    for (int nn = 0; nn < 16; nn++) acc[nn] = 0.f;
    int e = tid;
    for (int d = 0; d < 128; d++) {
        float tv = th[d * 128 + e];
#pragma unroll
        for (int nn = 0; nn < 16; nn++) acc[nn] += As[nn][d] * tv;
    }
    int c = b * 128 + e;
#pragma unroll
    for (int nn = 0; nn < 16; nn++)
        X[fblk(c, n0 + nn)] = __float2bfloat16(acc[nn]);
}

// ---------------- K8: bf16 HMMA GEMM with bulk-copy loads ----------------
// Blocked A [kc][2048 rows][64k], blocked B [kc][1024 rows][64k].
// bSel: 0=B1b(shared) 1=T1b 2=X2b 3=T2b ; oSel: 0=g_hyp4 per-z [node][c] 1=T1b 2=F1b 3=T2b
#define STG 32768               // per-stage: A 16KB + B 16KB
#define NST 3
#define STP 129                 // epilogue stage pitch (floats)
__global__ void __launch_bounds__(256, 2) k_mmagemm(
        const __nv_bfloat16* __restrict__ Abase, int bSel, int oSel,
        const float* __restrict__ rowscale, const float* __restrict__ parv, int leaky) {
    extern __shared__ char dsm[];
    char* sm = (char*)(((uintptr_t)dsm + 1023) & ~(uintptr_t)1023);
    uint32_t sb = s2u(sm);
    uint32_t barb = sb + NST * STG;             // 3 mbarriers, 8B each
    int tid = threadIdx.x, wid = tid >> 5, lane = tid & 31;
    int z = blockIdx.z;
    int m0 = blockIdx.y * 128, n0 = blockIdx.x * 128;

    const __nv_bfloat16* Ap = Abase + (size_t)z * WZ;
    size_t bz = (size_t)z * FZ;
    const __nv_bfloat16* Bp;
    if (bSel == 0)      Bp = g_B1b;
    else if (bSel == 1) Bp = g_T1b + bz;
    else if (bSel == 2) Bp = g_X2b + bz;
    else                Bp = g_T2b + bz;

    if (tid == 0) {
        MBAR_INIT(barb, 1u); MBAR_INIT(barb + 8, 1u); MBAR_INIT(barb + 16, 1u);
    }
    __syncthreads();

    auto issue = [&](int ck, int buf) {
        uint32_t bar = barb + buf * 8;
        MBAR_EXPECT(bar, 32768u);
        bulk_g2s(sb + buf * STG,         Ap + (((size_t)(ck * 2048 + m0)) << 6), 16384u, bar);
        bulk_g2s(sb + buf * STG + 16384, Bp + (((size_t)(ck * 1024 + n0)) << 6), 16384u, bar);
    };
    if (tid == 0) { issue(0, 0); issue(1, 1); }

    float acc[4][4][4];
#pragma unroll
    for (int i = 0; i < 4; i++)
#pragma unroll
        for (int j = 0; j < 4; j++)
#pragma unroll
            for (int r = 0; r < 4; r++) acc[i][j][r] = 0.f;

    int wm = (wid & 1) * 64;        // warp m offset (2 x 64)
    int wn = (wid >> 1) * 32;       // warp n offset (4 x 32)
    uint32_t rsel = (lane & 15);
    uint32_t csel = ((lane >> 4) & 1) * 16;
    uint32_t swz = (rsel & 7) << 4;

    int buf = 0;
    for (int ck = 0; ck < KC; ck++) {
        MBAR_WAIT(barb + buf * 8, (uint32_t)((ck / NST) & 1));
        uint32_t base = sb + buf * STG;
#pragma unroll
        for (int sub = 0; sub < 4; sub++) {
            uint32_t cb = (csel + sub * 32) ^ swz;
            uint32_t ah[4][4], bh[4][2];
#pragma unroll
            for (int mi = 0; mi < 4; mi++)
                ldmat4(ah[mi], base + (wm + mi * 16 + rsel) * 128 + cb);
#pragma unroll
            for (int nj = 0; nj < 2; nj++) {
                uint32_t r4[4];
                ldmat4(r4, base + 16384 + (wn + nj * 16 + rsel) * 128 + cb);
                bh[nj * 2][0] = r4[0]; bh[nj * 2][1] = r4[2];
                bh[nj * 2 + 1][0] = r4[1]; bh[nj * 2 + 1][1] = r4[3];
            }
#pragma unroll
            for (int mi = 0; mi < 4; mi++)
#pragma unroll
                for (int ni = 0; ni < 4; ni++)
                    mma16816(acc[mi][ni], ah[mi], bh[ni]);
        }
        __syncthreads();                       // all warps done reading buf
        if (tid == 0 && ck + 2 < KC) issue(ck + 2, (buf + 2 >= NST) ? buf + 2 - NST : buf + 2);
        buf = (buf + 1 == NST) ? 0 : buf + 1;
    }
    __syncthreads();

    // ---- epilogue: scale / leaky / alpha, two 64-c passes through SMEM stage ----
    float alpha = parv ? parv[z] : 1.f;
    float* st = (float*)sm;                 // [64][STP] fp32
    int mlo0 = wm + (lane >> 2);
    float rsv[8];
#pragma unroll
    for (int mi = 0; mi < 4; mi++) {
        int mlo = mlo0 + mi * 16;
        rsv[mi * 2]     = rowscale ? ((m0 + mlo < 2000) ? rowscale[m0 + mlo] : 0.f) : 1.f;
        rsv[mi * 2 + 1] = rowscale ? ((m0 + mlo + 8 < 2000) ? rowscale[m0 + mlo + 8] : 0.f) : 1.f;
    }
    __nv_bfloat16* C = nullptr;
    float* H = nullptr;
    if (oSel == 0)      H = g_hyp4 + (size_t)z * 2048000;
    else if (oSel == 1) C = g_T1b + bz;
    else if (oSel == 2) C = g_F1b + bz;
    else                C = g_T2b + bz;

    for (int p = 0; p < 2; p++) {
        if ((wn >> 6) == p) {
            int wnl = wn - p * 64;
#pragma unroll
            for (int mi = 0; mi < 4; mi++) {
                int mlo = mlo0 + mi * 16;
#pragma unroll
                for (int ni = 0; ni < 4; ni++) {
                    int nl = wnl + ni * 8 + (lane & 3) * 2;
#pragma unroll
                    for (int r = 0; r < 4; r++) {
                        float v = acc[mi][ni][r];
                        int ml = (r < 2) ? mlo : (mlo + 8);
                        v *= rsv[mi * 2 + (r < 2 ? 0 : 1)];
                        if (leaky) v = (v > 0.f) ? v : SLOPE * v;
                        v *= alpha;
                        st[(nl + (r & 1)) * STP + ml] = v;
                    }
                }
            }
        }
        __syncthreads();
        if (oSel == 0) {
            // coalesced [node][c] stores: consecutive tid -> consecutive c
            for (int idx = tid; idx < 8192; idx += 256) {
                int node = idx >> 6, cl = idx & 63;
                if (m0 + node < 2000)
                    H[(size_t)(m0 + node) * 1024 + n0 + p * 64 + cl] = st[cl * STP + node];
            }
        } else {
            for (int idx = tid; idx < 8192; idx += 256) {
                int nl = idx >> 7, ml = idx & 127;
                C[fblk(n0 + p * 64 + nl, m0 + ml)] = __float2bfloat16(st[nl * STP + ml]);
            }
        }
        __syncthreads();
    }
}

// ---------------- K9: final MLP (coalesced hyp reads, sum over z) ----------------
__global__ void __launch_bounds__(256) k_mlp(
                      const float* __restrict__ w1, const float* __restrict__ b1m,
                      const float* __restrict__ w2, const float* __restrict__ b2m,
                      float* __restrict__ out) {
    __shared__ float sw1[256], sb1[16], sw2[16], sb2;
    int tid = threadIdx.x;
    sw1[tid] = w1[tid];
    if (tid < 16) { sb1[tid] = b1m[tid]; sw2[tid] = w2[tid]; }
    if (tid == 0) sb2 = b2m[0];
    __syncthreads();
    int idx = blockIdx.x * 256 + tid;
    int b = idx / 32000; int rem = idx - b * 32000;
    int n = rem >> 4; int t = rem & 15;
    float cat[16];
    const float* xf = g_Xf + ((size_t)b * 2000 + n) * 128 + t * 8;
    const float* hz = g_hyp4 + (size_t)n * 1024 + b * 128 + t * 8;
#pragma unroll
    for (int j = 0; j < 8; j++) {
        cat[j] = xf[j];
        cat[8 + j] = hz[j] + hz[2048000 + j] + hz[4096000 + j] + hz[6144000 + j];
    }
    float acc = sb2;
#pragma unroll
    for (int i = 0; i < 16; i++) {
        float mi = sb1[i];
#pragma unroll
        for (int j = 0; j < 16; j++) mi += cat[j] * sw1[j * 16 + i];
        mi = fmaxf(mi, 0.f);
        acc += mi * sw2[i];
    }
    out[idx] = acc;
}

// ---------------- launch ----------------
#define GSMEM (NST * STG + 64 + 1024)   // stages + mbarriers + align slack

extern "C" void kernel_launch(void* const* d_in, const int* in_sizes, int n_in,
                              void* d_out, int out_size) {
    const float* inp  = (const float*)d_in[0];
    const float* embW = (const float*)d_in[1];
    const float* embB = (const float*)d_in[2];
    const float* W1   = (const float*)d_in[3];
    const float* U1   = (const float*)d_in[4];
    const float* b1   = (const float*)d_in[5];
    const float* ln1g = (const float*)d_in[6];
    const float* ln1b = (const float*)d_in[7];
    const float* W2   = (const float*)d_in[8];
    const float* U2   = (const float*)d_in[9];
    const float* b2   = (const float*)d_in[10];
    const float* Wq   = (const float*)d_in[11];
    const float* Wk   = (const float*)d_in[12];
    const float* Wv   = (const float*)d_in[13];
    const float* Wo   = (const float*)d_in[14];
    const float* ln2g = (const float*)d_in[15];
    const float* ln2b = (const float*)d_in[16];
    const float* par  = (const float*)d_in[17];
    const float* th1  = (const float*)d_in[18];
    const float* dg1  = (const float*)d_in[19];
    const float* th2  = (const float*)d_in[20];
    const float* dg2  = (const float*)d_in[21];
    const float* m1W  = (const float*)d_in[22];
    const float* m1b  = (const float*)d_in[23];
    const float* m2W  = (const float*)d_in[24];
    const float* m2b  = (const float*)d_in[25];
    const float* wav  = (const float*)d_in[26];
    const float* winv = (const float*)d_in[27];
    float* out = (float*)d_out;

    cudaFuncSetAttribute(k_mmagemm, cudaFuncAttributeMaxDynamicSharedMemorySize, GSMEM);

    __nv_bfloat16* wiB;  cudaGetSymbolAddress((void**)&wiB,  g_wiB);
    __nv_bfloat16* wavB; cudaGetSymbolAddress((void**)&wavB, g_wavB);

    k_zero<<<12, 256>>>();
    k_cvtB<<<31250, 256>>>(wav, winv);
    k_lstm1<<<4000, 128>>>(inp, embW, embB, W1, U1, b1);
    k_ln1<<<128, 1024>>>(ln1g, ln1b);
    k_lstm2<<<4000, 128>>>(W2, U2, b2);
    k_qkv<<<160, 256>>>(Wq, Wk, Wv);
    k_attn<<<32, 32>>>();
    k_oproj<<<128, 256>>>(Wo, ln2g, ln2b);

    // hypergraph, layer 1
    k_theta1<<<dim3(125, 8), 128>>>(th1);                                          // B1 = (Xf@th1)^T
    k_mmagemm<<<dim3(8, 16, 4), 256, GSMEM>>>(wiB,  0, 1, dg1, nullptr, 0);        // T1 = diag1*(Winv@X1)
    k_mmagemm<<<dim3(8, 16, 4), 256, GSMEM>>>(wavB, 1, 2, nullptr, nullptr, 1);    // F1 = leaky(W@T1)
    // layer 2
    k_theta2<<<dim3(125, 8, 4), 128>>>(th2);                                       // X2 = F1@th2
    k_mmagemm<<<dim3(8, 16, 4), 256, GSMEM>>>(wiB,  2, 3, dg2, nullptr, 0);        // T2 = diag2*(Winv@X2)
    k_mmagemm<<<dim3(8, 16, 4), 256, GSMEM>>>(wavB, 3, 0, nullptr, par, 1);        // hyp_z = par*leaky(W@T2)

    k_mlp<<<1000, 256>>>(m1W, m1b, m2W, m2b, out);
}